// round 4
// baseline (speedup 1.0000x reference)
#include <cuda_runtime.h>
#include <math.h>
#include <stdint.h>

// Problem constants
constexpr int cB  = 8;
constexpr int cSQ = 512;
constexpr int cSK = 1024;
constexpr int cD  = 1024;
constexpr int cH  = 16;
constexpr int cDK = 64;
constexpr int cF  = 4096;

// ---------------------------------------------------------------------------
// Scratch (device globals; no allocations allowed)
// ---------------------------------------------------------------------------
__device__ float g_bufQ [(size_t)cB*cSQ*cD];
__device__ float g_bufK [(size_t)cB*cSK*cD];
__device__ float g_bufV [(size_t)cB*cSK*cD];
__device__ float g_bufS [(size_t)cB*cH*cSQ*cSQ];
__device__ float g_bufC [(size_t)cB*cSQ*cD];
__device__ float g_bufO [(size_t)cB*cSQ*cD];
__device__ float g_bufX1[(size_t)cB*cSQ*cD];
__device__ float g_bufX2[(size_t)cB*cSQ*cD];
__device__ float g_bufF [(size_t)cB*cSQ*cF];

// ---------------------------------------------------------------------------
// helpers
// ---------------------------------------------------------------------------
__device__ __forceinline__ uint32_t f2tf(float f) {
    uint32_t r;
    asm("cvt.rna.tf32.f32 %0, %1;" : "=r"(r) : "f"(f));
    return r;
}

__device__ __forceinline__ void mma_tf32(float c[4],
    uint32_t a0, uint32_t a1, uint32_t a2, uint32_t a3,
    uint32_t b0, uint32_t b1)
{
    asm volatile(
        "mma.sync.aligned.m16n8k8.row.col.f32.tf32.tf32.f32 "
        "{%0,%1,%2,%3}, {%4,%5,%6,%7}, {%8,%9}, {%0,%1,%2,%3};"
        : "+f"(c[0]), "+f"(c[1]), "+f"(c[2]), "+f"(c[3])
        : "r"(a0), "r"(a1), "r"(a2), "r"(a3), "r"(b0), "r"(b1));
}

__device__ __forceinline__ void cp16(void* smem_dst, const void* gsrc) {
    uint32_t s = (uint32_t)__cvta_generic_to_shared(smem_dst);
    asm volatile("cp.async.ca.shared.global [%0], [%1], 16;" :: "r"(s), "l"(gsrc));
}
__device__ __forceinline__ void cp_commit() {
    asm volatile("cp.async.commit_group;");
}
template<int N>
__device__ __forceinline__ void cp_wait() {
    asm volatile("cp.async.wait_group %0;" :: "n"(N));
}

// ---------------------------------------------------------------------------
// tf32 GEMM v2: C[M,N] = A[M,K] @ W[K,N] + bias (+ReLU).
// 128x128 block, 4 warps (2x2), warp tile 64x64, k-step 16,
// 2-stage cp.async double buffering (raw fp32 in smem, cvt at frag load).
// As stride 20 words, Bs stride 136 words -> conflict-free frag LDS.
// ---------------------------------------------------------------------------
template<bool RELU>
__global__ __launch_bounds__(128) void gemm_tf32_v2(
    const float* __restrict__ A, const float* __restrict__ W,
    const float* __restrict__ bias, float* __restrict__ C,
    int M, int N, int K)
{
    __shared__ float As[2][128 * 20];
    __shared__ float Bs[2][16 * 136];

    const int tid  = threadIdx.x;
    const int bx   = blockIdx.x, by = blockIdx.y;
    const int warp = tid >> 5, lane = tid & 31;
    const int g = lane >> 2, tig = lane & 3;
    const int wm = warp >> 1;      // 0..1 -> 64 rows
    const int wn = warp & 1;       // 0..1 -> 64 cols

    const float* Arow = A + (size_t)(by*128 + tid)*K;                 // one row/thread
    const float* Bsrc = W + (size_t)(tid >> 5)*N + bx*128 + lane*4;   // rows (tid>>5)+4j

    const int nk = K >> 4;

    float acc[4][8][4] = {};

    // prefetch stage 0
    {
#pragma unroll
        for (int c = 0; c < 4; c++)
            cp16(&As[0][tid*20 + c*4], Arow + c*4);
#pragma unroll
        for (int j = 0; j < 4; j++)
            cp16(&Bs[0][((tid>>5) + j*4)*136 + lane*4], Bsrc + (size_t)(j*4)*N);
    }
    cp_commit();

    for (int kt = 0; kt < nk; kt++) {
        const int k0 = kt << 4;
        if (kt + 1 < nk) {
            const int s = (kt + 1) & 1;
            const int kn = k0 + 16;
#pragma unroll
            for (int c = 0; c < 4; c++)
                cp16(&As[s][tid*20 + c*4], Arow + kn + c*4);
#pragma unroll
            for (int j = 0; j < 4; j++)
                cp16(&Bs[s][((tid>>5) + j*4)*136 + lane*4], Bsrc + (size_t)(kn + j*4)*N);
        }
        cp_commit();                 // always commit (possibly empty group)
        cp_wait<1>();                // oldest group (this stage) complete
        __syncthreads();

        const float* as = As[kt & 1];
        const float* bs = Bs[kt & 1];

#pragma unroll
        for (int kk = 0; kk < 16; kk += 8) {
            uint32_t afr[4][4];
#pragma unroll
            for (int mt = 0; mt < 4; mt++) {
                int r0 = wm*64 + mt*16 + g;
                afr[mt][0] = f2tf(as[r0*20 + kk + tig]);
                afr[mt][1] = f2tf(as[(r0 + 8)*20 + kk + tig]);
                afr[mt][2] = f2tf(as[r0*20 + kk + 4 + tig]);
                afr[mt][3] = f2tf(as[(r0 + 8)*20 + kk + 4 + tig]);
            }
            uint32_t bfr[8][2];
#pragma unroll
            for (int nt = 0; nt < 8; nt++) {
                int n = wn*64 + nt*8 + g;
                bfr[nt][0] = f2tf(bs[(kk + tig)*136 + n]);
                bfr[nt][1] = f2tf(bs[(kk + 4 + tig)*136 + n]);
            }
#pragma unroll
            for (int mt = 0; mt < 4; mt++)
#pragma unroll
                for (int nt = 0; nt < 8; nt++)
                    mma_tf32(acc[mt][nt], afr[mt][0], afr[mt][1], afr[mt][2], afr[mt][3],
                             bfr[nt][0], bfr[nt][1]);
        }
        __syncthreads();
    }

#pragma unroll
    for (int mt = 0; mt < 4; mt++) {
#pragma unroll
        for (int nt = 0; nt < 8; nt++) {
            int row0 = by*128 + wm*64 + mt*16 + g;
            int col  = bx*128 + wn*64 + nt*8 + 2*tig;
            float b0 = bias[col], b1 = bias[col + 1];
            float2 v0 = { acc[mt][nt][0] + b0, acc[mt][nt][1] + b1 };
            float2 v1 = { acc[mt][nt][2] + b0, acc[mt][nt][3] + b1 };
            if (RELU) {
                v0.x = fmaxf(v0.x, 0.f); v0.y = fmaxf(v0.y, 0.f);
                v1.x = fmaxf(v1.x, 0.f); v1.y = fmaxf(v1.y, 0.f);
            }
            *(float2*)&C[(size_t)row0*N + col]       = v0;
            *(float2*)&C[(size_t)(row0 + 8)*N + col] = v1;
        }
    }
}

// ---------------------------------------------------------------------------
// QK^T via tf32 mma. Block = 64 q x 64 k. grid = (sk/64, SQ/64, B*H).
// ---------------------------------------------------------------------------
__global__ __launch_bounds__(256) void qk_mma_kernel(
    const float* __restrict__ Q, const float* __restrict__ Km,
    float* __restrict__ S, const int* __restrict__ kvmask,
    int sk, int causal, float scale)
{
    __shared__ uint32_t Qs[64 * 68];
    __shared__ uint32_t Ks[64 * 68];
    __shared__ int msk[64];

    const int bh = blockIdx.z;
    const int b  = bh >> 4, h = bh & 15;
    const int q0 = blockIdx.y * 64;
    const int k0 = blockIdx.x * 64;
    const int tid  = threadIdx.x;
    const int warp = tid >> 5, lane = tid & 31;
    const int g = lane >> 2, tig = lane & 3;
    const int wm = warp >> 2;
    const int wn = warp & 3;

    if (causal && k0 > q0 + 63) {
        float4 ninf = { -INFINITY, -INFINITY, -INFINITY, -INFINITY };
#pragma unroll
        for (int it = 0; it < 4; it++) {
            int idx = tid + it * 256;
            int r = idx >> 4, c4 = (idx & 15) * 4;
            *(float4*)(S + ((size_t)bh*cSQ + q0 + r)*sk + k0 + c4) = ninf;
        }
        return;
    }

    const float* Qbase = Q  + ((size_t)b*cSQ + q0)*cD + h*cDK;
    const float* Kbase = Km + ((size_t)b*sk  + k0)*cD + h*cDK;
#pragma unroll
    for (int it = 0; it < 4; it++) {
        int idx = tid + it * 256;
        int r = idx >> 4, c4 = (idx & 15) * 4;
        float4 v = *(const float4*)(Qbase + (size_t)r*cD + c4);
        uint4 u = { f2tf(v.x), f2tf(v.y), f2tf(v.z), f2tf(v.w) };
        *(uint4*)&Qs[r*68 + c4] = u;
        float4 w = *(const float4*)(Kbase + (size_t)r*cD + c4);
        uint4 t = { f2tf(w.x), f2tf(w.y), f2tf(w.z), f2tf(w.w) };
        *(uint4*)&Ks[r*68 + c4] = t;
    }
    if (kvmask && tid < 64) msk[tid] = kvmask[b*sk + k0 + tid];
    __syncthreads();

    float acc[2][2][4] = {};
#pragma unroll
    for (int kk = 0; kk < 64; kk += 8) {
        uint32_t bf[2][2];
#pragma unroll
        for (int nt = 0; nt < 2; nt++) {
            int n = wn*16 + nt*8 + g;
            bf[nt][0] = Ks[n*68 + kk + tig];
            bf[nt][1] = Ks[n*68 + kk + 4 + tig];
        }
        uint32_t af[2][4];
#pragma unroll
        for (int mt = 0; mt < 2; mt++) {
            int r0 = wm*32 + mt*16 + g;
            af[mt][0] = Qs[r0*68 + kk + tig];
            af[mt][1] = Qs[(r0 + 8)*68 + kk + tig];
            af[mt][2] = Qs[r0*68 + kk + 4 + tig];
            af[mt][3] = Qs[(r0 + 8)*68 + kk + 4 + tig];
        }
#pragma unroll
        for (int mt = 0; mt < 2; mt++)
#pragma unroll
            for (int nt = 0; nt < 2; nt++)
                mma_tf32(acc[mt][nt], af[mt][0], af[mt][1], af[mt][2], af[mt][3],
                         bf[nt][0], bf[nt][1]);
    }

#pragma unroll
    for (int mt = 0; mt < 2; mt++) {
#pragma unroll
        for (int nt = 0; nt < 2; nt++) {
            int qrow = q0 + wm*32 + mt*16 + g;
            int kl   = wn*16 + nt*8 + 2*tig;
            int kcol = k0 + kl;
            bool m0 = kvmask && msk[kl] == 0;
            bool m1 = kvmask && msk[kl + 1] == 0;
#pragma unroll
            for (int rr = 0; rr < 2; rr++) {
                int q = qrow + rr*8;
                float v0 = acc[mt][nt][rr*2 + 0] * scale;
                float v1 = acc[mt][nt][rr*2 + 1] * scale;
                if ((causal && kcol     > q) || m0) v0 = -INFINITY;
                if ((causal && kcol + 1 > q) || m1) v1 = -INFINITY;
                float2 v = { v0, v1 };
                *(float2*)&S[((size_t)bh*cSQ + q)*sk + kcol] = v;
            }
        }
    }
}

// ---------------------------------------------------------------------------
// A @ V via tf32 mma. Block = 64 q x 64 d (one head). grid = (SQ/64, B*H).
// ---------------------------------------------------------------------------
__global__ __launch_bounds__(256) void av_mma_kernel(
    const float* __restrict__ P, const float* __restrict__ V,
    float* __restrict__ O, int sk, int causal)
{
    __shared__ uint32_t Ps[64 * 36];
    __shared__ uint32_t Vs[32 * 72];

    const int bh = blockIdx.y;
    const int b  = bh >> 4, h = bh & 15;
    const int q0 = blockIdx.x * 64;
    const int tid  = threadIdx.x;
    const int warp = tid >> 5, lane = tid & 31;
    const int g = lane >> 2, tig = lane & 3;
    const int wm = warp >> 2;
    const int wn = warp & 3;

    const float* Pbase = P + ((size_t)bh*cSQ + q0)*sk;
    const float* Vbase = V + ((size_t)b*sk)*cD + h*cDK;

    float acc[2][2][4] = {};
    const int kend = causal ? (q0 + 64) : sk;

    for (int k0 = 0; k0 < kend; k0 += 32) {
#pragma unroll
        for (int it = 0; it < 2; it++) {
            int idx = tid + it * 256;
            {
                int r = idx >> 3, c4 = (idx & 7) * 4;
                float4 v = *(const float4*)(Pbase + (size_t)r*sk + k0 + c4);
                uint4 u = { f2tf(v.x), f2tf(v.y), f2tf(v.z), f2tf(v.w) };
                *(uint4*)&Ps[r*36 + c4] = u;
            }
            {
                int r = idx >> 4, c4 = (idx & 15) * 4;
                float4 v = *(const float4*)(Vbase + (size_t)(k0 + r)*cD + c4);
                uint4 u = { f2tf(v.x), f2tf(v.y), f2tf(v.z), f2tf(v.w) };
                *(uint4*)&Vs[r*72 + c4] = u;
            }
        }
        __syncthreads();

#pragma unroll
        for (int kk = 0; kk < 32; kk += 8) {
            uint32_t bf[2][2];
#pragma unroll
            for (int nt = 0; nt < 2; nt++) {
                int n = wn*16 + nt*8 + g;
                bf[nt][0] = Vs[(kk + tig)*72 + n];
                bf[nt][1] = Vs[(kk + 4 + tig)*72 + n];
            }
            uint32_t af[2][4];
#pragma unroll
            for (int mt = 0; mt < 2; mt++) {
                int r0 = wm*32 + mt*16 + g;
                af[mt][0] = Ps[r0*36 + kk + tig];
                af[mt][1] = Ps[(r0 + 8)*36 + kk + tig];
                af[mt][2] = Ps[r0*36 + kk + 4 + tig];
                af[mt][3] = Ps[(r0 + 8)*36 + kk + 4 + tig];
            }
#pragma unroll
            for (int mt = 0; mt < 2; mt++)
#pragma unroll
                for (int nt = 0; nt < 2; nt++)
                    mma_tf32(acc[mt][nt], af[mt][0], af[mt][1], af[mt][2], af[mt][3],
                             bf[nt][0], bf[nt][1]);
        }
        __syncthreads();
    }

#pragma unroll
    for (int mt = 0; mt < 2; mt++) {
#pragma unroll
        for (int nt = 0; nt < 2; nt++) {
            int qrow = q0 + wm*32 + mt*16 + g;
            int d    = wn*16 + nt*8 + 2*tig;
#pragma unroll
            for (int rr = 0; rr < 2; rr++) {
                size_t row = (size_t)b*cSQ + qrow + rr*8;
                float2 v = { acc[mt][nt][rr*2 + 0], acc[mt][nt][rr*2 + 1] };
                *(float2*)&O[row*cD + h*cDK + d] = v;
            }
        }
    }
}

// ---------------------------------------------------------------------------
// Register-resident row softmax. One block (256 threads) per row.
// VEC = elems/thread (2 for L=512, 4 for L=1024). One read + one write.
// ---------------------------------------------------------------------------
template<int VEC>
__global__ __launch_bounds__(256) void softmax_reg_kernel(float* __restrict__ S)
{
    __shared__ float redm[8];
    __shared__ float reds[8];
    float* p = S + (size_t)blockIdx.x * (256 * VEC);
    const int t = threadIdx.x;
    const int warp = t >> 5, lane = t & 31;

    float v[VEC];
#pragma unroll
    for (int i = 0; i < VEC; i++) v[i] = p[t*VEC + i];

    float m = v[0];
#pragma unroll
    for (int i = 1; i < VEC; i++) m = fmaxf(m, v[i]);
#pragma unroll
    for (int off = 16; off > 0; off >>= 1)
        m = fmaxf(m, __shfl_xor_sync(0xffffffffu, m, off));
    if (lane == 0) redm[warp] = m;
    __syncthreads();
    float bm = redm[0];
#pragma unroll
    for (int i = 1; i < 8; i++) bm = fmaxf(bm, redm[i]);

    float s = 0.f;
#pragma unroll
    for (int i = 0; i < VEC; i++) {
        v[i] = __expf(v[i] - bm);
        s += v[i];
    }
#pragma unroll
    for (int off = 16; off > 0; off >>= 1)
        s += __shfl_xor_sync(0xffffffffu, s, off);
    if (lane == 0) reds[warp] = s;
    __syncthreads();
    float bs = reds[0];
#pragma unroll
    for (int i = 1; i < 8; i++) bs += reds[i];

    float inv = 1.0f / bs;
#pragma unroll
    for (int i = 0; i < VEC; i++) p[t*VEC + i] = v[i] * inv;
}

// ---------------------------------------------------------------------------
// out = LayerNorm(X + R) * g + b over last dim (D=1024). One block per row.
// ---------------------------------------------------------------------------
__global__ __launch_bounds__(256) void ln_residual_kernel(
    const float* __restrict__ X, const float* __restrict__ R,
    const float* __restrict__ g, const float* __restrict__ be,
    float* __restrict__ out)
{
    __shared__ float red[256];
    const size_t row = blockIdx.x;
    const int t = threadIdx.x;
    const float* xr = X + row*cD;
    const float* rr = R + row*cD;

    float v[4]; float s = 0.f;
#pragma unroll
    for (int i = 0; i < 4; i++) { v[i] = xr[t + i*256] + rr[t + i*256]; s += v[i]; }
    red[t] = s; __syncthreads();
    for (int k = 128; k > 0; k >>= 1) { if (t < k) red[t] += red[t+k]; __syncthreads(); }
    float mu = red[0] * (1.0f / cD); __syncthreads();

    float vs = 0.f;
#pragma unroll
    for (int i = 0; i < 4; i++) { float d = v[i] - mu; vs += d*d; }
    red[t] = vs; __syncthreads();
    for (int k = 128; k > 0; k >>= 1) { if (t < k) red[t] += red[t+k]; __syncthreads(); }
    float inv = rsqrtf(red[0] * (1.0f / cD) + 1e-5f);

    float* orow = out + row*cD;
#pragma unroll
    for (int i = 0; i < 4; i++) {
        int c = t + i*256;
        orow[c] = (v[i] - mu) * inv * g[c] + be[c];
    }
}

// ---------------------------------------------------------------------------
// Launch
// ---------------------------------------------------------------------------
extern "C" void kernel_launch(void* const* d_in, const int* in_sizes, int n_in,
                              void* d_out, int out_size)
{
    const float* x        = (const float*)d_in[0];
    const float* enc_o    = (const float*)d_in[1];
    const int*   enc_mask = (const int*)  d_in[2];
    const float* a1_wq = (const float*)d_in[3];
    const float* a1_bq = (const float*)d_in[4];
    const float* a1_wk = (const float*)d_in[5];
    const float* a1_bk = (const float*)d_in[6];
    const float* a1_wv = (const float*)d_in[7];
    const float* a1_bv = (const float*)d_in[8];
    const float* a1_wo = (const float*)d_in[9];
    const float* a1_bo = (const float*)d_in[10];
    const float* a2_wq = (const float*)d_in[11];
    const float* a2_bq = (const float*)d_in[12];
    const float* a2_wk = (const float*)d_in[13];
    const float* a2_bk = (const float*)d_in[14];
    const float* a2_wv = (const float*)d_in[15];
    const float* a2_bv = (const float*)d_in[16];
    const float* a2_wo = (const float*)d_in[17];
    const float* a2_bo = (const float*)d_in[18];
    const float* ff_w1 = (const float*)d_in[19];
    const float* ff_b1 = (const float*)d_in[20];
    const float* ff_w2 = (const float*)d_in[21];
    const float* ff_b2 = (const float*)d_in[22];
    const float* ln1_g = (const float*)d_in[23];
    const float* ln1_b = (const float*)d_in[24];
    const float* ln2_g = (const float*)d_in[25];
    const float* ln2_b = (const float*)d_in[26];
    const float* ln3_g = (const float*)d_in[27];
    const float* ln3_b = (const float*)d_in[28];

    float* out_x    = (float*)d_out;
    float* out_attn = out_x + (size_t)cB*cSQ*cD;

    float *bufQ, *bufK, *bufV, *bufS, *bufC, *bufO, *bufX1, *bufX2, *bufF;
    cudaGetSymbolAddress((void**)&bufQ,  g_bufQ);
    cudaGetSymbolAddress((void**)&bufK,  g_bufK);
    cudaGetSymbolAddress((void**)&bufV,  g_bufV);
    cudaGetSymbolAddress((void**)&bufS,  g_bufS);
    cudaGetSymbolAddress((void**)&bufC,  g_bufC);
    cudaGetSymbolAddress((void**)&bufO,  g_bufO);
    cudaGetSymbolAddress((void**)&bufX1, g_bufX1);
    cudaGetSymbolAddress((void**)&bufX2, g_bufX2);
    cudaGetSymbolAddress((void**)&bufF,  g_bufF);

    const float scale = 0.125f;   // 1/sqrt(64)
    const dim3 blk128(128), blk(256);
    const int M1 = cB * cSQ;      // 4096
    const int M2 = cB * cSK;      // 8192

    // ---- self-attention (causal) ----
    gemm_tf32_v2<false><<<dim3(cD/128, M1/128), blk128>>>(x, a1_wq, a1_bq, bufQ, M1, cD, cD);
    gemm_tf32_v2<false><<<dim3(cD/128, M1/128), blk128>>>(x, a1_wk, a1_bk, bufK, M1, cD, cD);
    gemm_tf32_v2<false><<<dim3(cD/128, M1/128), blk128>>>(x, a1_wv, a1_bv, bufV, M1, cD, cD);
    qk_mma_kernel<<<dim3(cSQ/64, cSQ/64, cB*cH), blk>>>(bufQ, bufK, bufS, nullptr, cSQ, 1, scale);
    softmax_reg_kernel<2><<<cB*cH*cSQ, blk>>>(bufS);
    av_mma_kernel<<<dim3(cSQ/64, cB*cH), blk>>>(bufS, bufV, bufC, cSQ, 1);
    gemm_tf32_v2<false><<<dim3(cD/128, M1/128), blk128>>>(bufC, a1_wo, a1_bo, bufO, M1, cD, cD);
    ln_residual_kernel<<<M1, blk>>>(x, bufO, ln1_g, ln1_b, bufX1);

    // ---- cross-attention (kv mask); probs go straight into d_out ----
    gemm_tf32_v2<false><<<dim3(cD/128, M1/128), blk128>>>(bufX1, a2_wq, a2_bq, bufQ, M1, cD, cD);
    gemm_tf32_v2<false><<<dim3(cD/128, M2/128), blk128>>>(enc_o, a2_wk, a2_bk, bufK, M2, cD, cD);
    gemm_tf32_v2<false><<<dim3(cD/128, M2/128), blk128>>>(enc_o, a2_wv, a2_bv, bufV, M2, cD, cD);
    qk_mma_kernel<<<dim3(cSK/64, cSQ/64, cB*cH), blk>>>(bufQ, bufK, out_attn, enc_mask, cSK, 0, scale);
    softmax_reg_kernel<4><<<cB*cH*cSQ, blk>>>(out_attn);
    av_mma_kernel<<<dim3(cSQ/64, cB*cH), blk>>>(out_attn, bufV, bufC, cSK, 0);
    gemm_tf32_v2<false><<<dim3(cD/128, M1/128), blk128>>>(bufC, a2_wo, a2_bo, bufO, M1, cD, cD);
    ln_residual_kernel<<<M1, blk>>>(bufX1, bufO, ln2_g, ln2_b, bufX2);

    // ---- feed-forward ----
    gemm_tf32_v2<true ><<<dim3(cF/128, M1/128), blk128>>>(bufX2, ff_w1, ff_b1, bufF, M1, cF, cD);
    gemm_tf32_v2<false><<<dim3(cD/128, M1/128), blk128>>>(bufF, ff_w2, ff_b2, bufO, M1, cD, cF);
    ln_residual_kernel<<<M1, blk>>>(bufX2, bufO, ln3_g, ln3_b, out_x);
}

// round 5
// speedup vs baseline: 1.1746x; 1.1746x over previous
#include <cuda_runtime.h>
#include <math.h>
#include <stdint.h>

// Problem constants
constexpr int cB  = 8;
constexpr int cSQ = 512;
constexpr int cSK = 1024;
constexpr int cD  = 1024;
constexpr int cH  = 16;
constexpr int cDK = 64;
constexpr int cF  = 4096;

// ---------------------------------------------------------------------------
// Scratch (device globals; no allocations allowed)
// ---------------------------------------------------------------------------
__device__ float g_bufQ [(size_t)cB*cSQ*cD];
__device__ float g_bufK [(size_t)cB*cSK*cD];
__device__ float g_bufV [(size_t)cB*cSK*cD];
__device__ float g_bufS [(size_t)cB*cH*cSQ*cSQ];
__device__ float g_bufC [(size_t)cB*cSQ*cD];
__device__ float g_bufO [(size_t)cB*cSQ*cD];
__device__ float g_bufX1[(size_t)cB*cSQ*cD];
__device__ float g_bufX2[(size_t)cB*cSQ*cD];
__device__ float g_bufF [(size_t)cB*cSQ*cF];

// ---------------------------------------------------------------------------
// helpers
// ---------------------------------------------------------------------------
__device__ __forceinline__ uint32_t f2tf(float f) {
    uint32_t r;
    asm("cvt.rna.tf32.f32 %0, %1;" : "=r"(r) : "f"(f));
    return r;
}

__device__ __forceinline__ void mma_tf32(float c[4],
    uint32_t a0, uint32_t a1, uint32_t a2, uint32_t a3,
    uint32_t b0, uint32_t b1)
{
    asm volatile(
        "mma.sync.aligned.m16n8k8.row.col.f32.tf32.tf32.f32 "
        "{%0,%1,%2,%3}, {%4,%5,%6,%7}, {%8,%9}, {%0,%1,%2,%3};"
        : "+f"(c[0]), "+f"(c[1]), "+f"(c[2]), "+f"(c[3])
        : "r"(a0), "r"(a1), "r"(a2), "r"(a3), "r"(b0), "r"(b1));
}

__device__ __forceinline__ void cp16(void* smem_dst, const void* gsrc) {
    uint32_t s = (uint32_t)__cvta_generic_to_shared(smem_dst);
    asm volatile("cp.async.ca.shared.global [%0], [%1], 16;" :: "r"(s), "l"(gsrc));
}
__device__ __forceinline__ void cp_commit() {
    asm volatile("cp.async.commit_group;");
}
template<int N>
__device__ __forceinline__ void cp_wait() {
    asm volatile("cp.async.wait_group %0;" :: "n"(N));
}

// ---------------------------------------------------------------------------
// tf32 GEMM v3: C[M,N] = A[M,K] @ W[K,N] + bias (+ReLU).
// 128x128 block, 256 threads / 8 warps (2x4), warp tile 64x32, k-step 16,
// 2-stage cp.async double buffering (raw fp32 in smem; cvt.rna at frag load).
// As stride 20 words, Bs stride 136 words -> conflict-free frag LDS.
// ---------------------------------------------------------------------------
template<bool RELU>
__global__ __launch_bounds__(256) void gemm_tf32_v3(
    const float* __restrict__ A, const float* __restrict__ W,
    const float* __restrict__ bias, float* __restrict__ C,
    int M, int N, int K)
{
    __shared__ float As[2][128 * 20];
    __shared__ float Bs[2][16 * 136];

    const int tid  = threadIdx.x;
    const int bx   = blockIdx.x, by = blockIdx.y;
    const int warp = tid >> 5, lane = tid & 31;
    const int g = lane >> 2, tig = lane & 3;
    const int wm = warp >> 2;      // 0..1 -> 64 rows
    const int wn = warp & 3;       // 0..3 -> 32 cols

    // load mappings
    const int ar = tid >> 1;             // 0..127
    const int ac = (tid & 1) * 8;        // 0 or 8
    const int br = tid >> 5;             // 0..7 (also +8)
    const int bc = lane * 4;             // 0..124
    const float* Asrc = A + (size_t)(by*128 + ar)*K + ac;
    const float* Bsrc = W + bx*128 + bc;

    const int nk = K >> 4;

    float acc[4][4][4] = {};

    // prefetch stage 0
    {
        cp16(&As[0][ar*20 + ac],     Asrc);
        cp16(&As[0][ar*20 + ac + 4], Asrc + 4);
        cp16(&Bs[0][br*136 + bc],       Bsrc + (size_t)br*N);
        cp16(&Bs[0][(br + 8)*136 + bc], Bsrc + (size_t)(br + 8)*N);
    }
    cp_commit();

    for (int kt = 0; kt < nk; kt++) {
        if (kt + 1 < nk) {
            const int s = (kt + 1) & 1;
            const int kn = (kt + 1) << 4;
            cp16(&As[s][ar*20 + ac],     Asrc + kn);
            cp16(&As[s][ar*20 + ac + 4], Asrc + kn + 4);
            cp16(&Bs[s][br*136 + bc],       Bsrc + (size_t)(kn + br)*N);
            cp16(&Bs[s][(br + 8)*136 + bc], Bsrc + (size_t)(kn + br + 8)*N);
        }
        cp_commit();
        cp_wait<1>();
        __syncthreads();

        const float* as = As[kt & 1];
        const float* bs = Bs[kt & 1];

#pragma unroll
        for (int kk = 0; kk < 16; kk += 8) {
            uint32_t afr[4][4];
#pragma unroll
            for (int mt = 0; mt < 4; mt++) {
                int r0 = wm*64 + mt*16 + g;
                afr[mt][0] = f2tf(as[r0*20 + kk + tig]);
                afr[mt][1] = f2tf(as[(r0 + 8)*20 + kk + tig]);
                afr[mt][2] = f2tf(as[r0*20 + kk + 4 + tig]);
                afr[mt][3] = f2tf(as[(r0 + 8)*20 + kk + 4 + tig]);
            }
            uint32_t bfr[4][2];
#pragma unroll
            for (int nt = 0; nt < 4; nt++) {
                int n = wn*32 + nt*8 + g;
                bfr[nt][0] = f2tf(bs[(kk + tig)*136 + n]);
                bfr[nt][1] = f2tf(bs[(kk + 4 + tig)*136 + n]);
            }
#pragma unroll
            for (int mt = 0; mt < 4; mt++)
#pragma unroll
                for (int nt = 0; nt < 4; nt++)
                    mma_tf32(acc[mt][nt], afr[mt][0], afr[mt][1], afr[mt][2], afr[mt][3],
                             bfr[nt][0], bfr[nt][1]);
        }
        __syncthreads();
    }

#pragma unroll
    for (int mt = 0; mt < 4; mt++) {
#pragma unroll
        for (int nt = 0; nt < 4; nt++) {
            int row0 = by*128 + wm*64 + mt*16 + g;
            int col  = bx*128 + wn*32 + nt*8 + 2*tig;
            float b0 = bias[col], b1 = bias[col + 1];
            float2 v0 = { acc[mt][nt][0] + b0, acc[mt][nt][1] + b1 };
            float2 v1 = { acc[mt][nt][2] + b0, acc[mt][nt][3] + b1 };
            if (RELU) {
                v0.x = fmaxf(v0.x, 0.f); v0.y = fmaxf(v0.y, 0.f);
                v1.x = fmaxf(v1.x, 0.f); v1.y = fmaxf(v1.y, 0.f);
            }
            *(float2*)&C[(size_t)row0*N + col]       = v0;
            *(float2*)&C[(size_t)(row0 + 8)*N + col] = v1;
        }
    }
}

// ---------------------------------------------------------------------------
// QK^T via tf32 mma. Block = 64 q x 64 k. grid = (sk/64, SQ/64, B*H).
// ---------------------------------------------------------------------------
__global__ __launch_bounds__(256) void qk_mma_kernel(
    const float* __restrict__ Q, const float* __restrict__ Km,
    float* __restrict__ S, const int* __restrict__ kvmask,
    int sk, int causal, float scale)
{
    __shared__ uint32_t Qs[64 * 68];
    __shared__ uint32_t Ks[64 * 68];
    __shared__ int msk[64];

    const int bh = blockIdx.z;
    const int b  = bh >> 4, h = bh & 15;
    const int q0 = blockIdx.y * 64;
    const int k0 = blockIdx.x * 64;
    const int tid  = threadIdx.x;
    const int warp = tid >> 5, lane = tid & 31;
    const int g = lane >> 2, tig = lane & 3;
    const int wm = warp >> 2;
    const int wn = warp & 3;

    if (causal && k0 > q0 + 63) {
        float4 ninf = { -INFINITY, -INFINITY, -INFINITY, -INFINITY };
#pragma unroll
        for (int it = 0; it < 4; it++) {
            int idx = tid + it * 256;
            int r = idx >> 4, c4 = (idx & 15) * 4;
            *(float4*)(S + ((size_t)bh*cSQ + q0 + r)*sk + k0 + c4) = ninf;
        }
        return;
    }

    const float* Qbase = Q  + ((size_t)b*cSQ + q0)*cD + h*cDK;
    const float* Kbase = Km + ((size_t)b*sk  + k0)*cD + h*cDK;
#pragma unroll
    for (int it = 0; it < 4; it++) {
        int idx = tid + it * 256;
        int r = idx >> 4, c4 = (idx & 15) * 4;
        float4 v = *(const float4*)(Qbase + (size_t)r*cD + c4);
        uint4 u = { f2tf(v.x), f2tf(v.y), f2tf(v.z), f2tf(v.w) };
        *(uint4*)&Qs[r*68 + c4] = u;
        float4 w = *(const float4*)(Kbase + (size_t)r*cD + c4);
        uint4 t = { f2tf(w.x), f2tf(w.y), f2tf(w.z), f2tf(w.w) };
        *(uint4*)&Ks[r*68 + c4] = t;
    }
    if (kvmask && tid < 64) msk[tid] = kvmask[b*sk + k0 + tid];
    __syncthreads();

    float acc[2][2][4] = {};
#pragma unroll
    for (int kk = 0; kk < 64; kk += 8) {
        uint32_t bf[2][2];
#pragma unroll
        for (int nt = 0; nt < 2; nt++) {
            int n = wn*16 + nt*8 + g;
            bf[nt][0] = Ks[n*68 + kk + tig];
            bf[nt][1] = Ks[n*68 + kk + 4 + tig];
        }
        uint32_t af[2][4];
#pragma unroll
        for (int mt = 0; mt < 2; mt++) {
            int r0 = wm*32 + mt*16 + g;
            af[mt][0] = Qs[r0*68 + kk + tig];
            af[mt][1] = Qs[(r0 + 8)*68 + kk + tig];
            af[mt][2] = Qs[r0*68 + kk + 4 + tig];
            af[mt][3] = Qs[(r0 + 8)*68 + kk + 4 + tig];
        }
#pragma unroll
        for (int mt = 0; mt < 2; mt++)
#pragma unroll
            for (int nt = 0; nt < 2; nt++)
                mma_tf32(acc[mt][nt], af[mt][0], af[mt][1], af[mt][2], af[mt][3],
                         bf[nt][0], bf[nt][1]);
    }

#pragma unroll
    for (int mt = 0; mt < 2; mt++) {
#pragma unroll
        for (int nt = 0; nt < 2; nt++) {
            int qrow = q0 + wm*32 + mt*16 + g;
            int kl   = wn*16 + nt*8 + 2*tig;
            int kcol = k0 + kl;
            bool m0 = kvmask && msk[kl] == 0;
            bool m1 = kvmask && msk[kl + 1] == 0;
#pragma unroll
            for (int rr = 0; rr < 2; rr++) {
                int q = qrow + rr*8;
                float v0 = acc[mt][nt][rr*2 + 0] * scale;
                float v1 = acc[mt][nt][rr*2 + 1] * scale;
                if ((causal && kcol     > q) || m0) v0 = -INFINITY;
                if ((causal && kcol + 1 > q) || m1) v1 = -INFINITY;
                float2 v = { v0, v1 };
                *(float2*)&S[((size_t)bh*cSQ + q)*sk + kcol] = v;
            }
        }
    }
}

// ---------------------------------------------------------------------------
// A @ V via tf32 mma. Block = 64 q x 64 d (one head). grid = (SQ/64, B*H).
// ---------------------------------------------------------------------------
__global__ __launch_bounds__(256) void av_mma_kernel(
    const float* __restrict__ P, const float* __restrict__ V,
    float* __restrict__ O, int sk, int causal)
{
    __shared__ uint32_t Ps[64 * 36];
    __shared__ uint32_t Vs[32 * 72];

    const int bh = blockIdx.y;
    const int b  = bh >> 4, h = bh & 15;
    const int q0 = blockIdx.x * 64;
    const int tid  = threadIdx.x;
    const int warp = tid >> 5, lane = tid & 31;
    const int g = lane >> 2, tig = lane & 3;
    const int wm = warp >> 2;
    const int wn = warp & 3;

    const float* Pbase = P + ((size_t)bh*cSQ + q0)*sk;
    const float* Vbase = V + ((size_t)b*sk)*cD + h*cDK;

    float acc[2][2][4] = {};
    const int kend = causal ? (q0 + 64) : sk;

    for (int k0 = 0; k0 < kend; k0 += 32) {
#pragma unroll
        for (int it = 0; it < 2; it++) {
            int idx = tid + it * 256;
            {
                int r = idx >> 3, c4 = (idx & 7) * 4;
                float4 v = *(const float4*)(Pbase + (size_t)r*sk + k0 + c4);
                uint4 u = { f2tf(v.x), f2tf(v.y), f2tf(v.z), f2tf(v.w) };
                *(uint4*)&Ps[r*36 + c4] = u;
            }
            {
                int r = idx >> 4, c4 = (idx & 15) * 4;
                float4 v = *(const float4*)(Vbase + (size_t)(k0 + r)*cD + c4);
                uint4 u = { f2tf(v.x), f2tf(v.y), f2tf(v.z), f2tf(v.w) };
                *(uint4*)&Vs[r*72 + c4] = u;
            }
        }
        __syncthreads();

#pragma unroll
        for (int kk = 0; kk < 32; kk += 8) {
            uint32_t bf[2][2];
#pragma unroll
            for (int nt = 0; nt < 2; nt++) {
                int n = wn*16 + nt*8 + g;
                bf[nt][0] = Vs[(kk + tig)*72 + n];
                bf[nt][1] = Vs[(kk + 4 + tig)*72 + n];
            }
            uint32_t af[2][4];
#pragma unroll
            for (int mt = 0; mt < 2; mt++) {
                int r0 = wm*32 + mt*16 + g;
                af[mt][0] = Ps[r0*36 + kk + tig];
                af[mt][1] = Ps[(r0 + 8)*36 + kk + tig];
                af[mt][2] = Ps[r0*36 + kk + 4 + tig];
                af[mt][3] = Ps[(r0 + 8)*36 + kk + 4 + tig];
            }
#pragma unroll
            for (int mt = 0; mt < 2; mt++)
#pragma unroll
                for (int nt = 0; nt < 2; nt++)
                    mma_tf32(acc[mt][nt], af[mt][0], af[mt][1], af[mt][2], af[mt][3],
                             bf[nt][0], bf[nt][1]);
        }
        __syncthreads();
    }

#pragma unroll
    for (int mt = 0; mt < 2; mt++) {
#pragma unroll
        for (int nt = 0; nt < 2; nt++) {
            int qrow = q0 + wm*32 + mt*16 + g;
            int d    = wn*16 + nt*8 + 2*tig;
#pragma unroll
            for (int rr = 0; rr < 2; rr++) {
                size_t row = (size_t)b*cSQ + qrow + rr*8;
                float2 v = { acc[mt][nt][rr*2 + 0], acc[mt][nt][rr*2 + 1] };
                *(float2*)&O[row*cD + h*cDK + d] = v;
            }
        }
    }
}

// ---------------------------------------------------------------------------
// Register-resident row softmax. One block (256 threads) per row.
// ---------------------------------------------------------------------------
template<int VEC>
__global__ __launch_bounds__(256) void softmax_reg_kernel(float* __restrict__ S)
{
    __shared__ float redm[8];
    __shared__ float reds[8];
    float* p = S + (size_t)blockIdx.x * (256 * VEC);
    const int t = threadIdx.x;
    const int warp = t >> 5, lane = t & 31;

    float v[VEC];
#pragma unroll
    for (int i = 0; i < VEC; i++) v[i] = p[t*VEC + i];

    float m = v[0];
#pragma unroll
    for (int i = 1; i < VEC; i++) m = fmaxf(m, v[i]);
#pragma unroll
    for (int off = 16; off > 0; off >>= 1)
        m = fmaxf(m, __shfl_xor_sync(0xffffffffu, m, off));
    if (lane == 0) redm[warp] = m;
    __syncthreads();
    float bm = redm[0];
#pragma unroll
    for (int i = 1; i < 8; i++) bm = fmaxf(bm, redm[i]);

    float s = 0.f;
#pragma unroll
    for (int i = 0; i < VEC; i++) {
        v[i] = __expf(v[i] - bm);
        s += v[i];
    }
#pragma unroll
    for (int off = 16; off > 0; off >>= 1)
        s += __shfl_xor_sync(0xffffffffu, s, off);
    if (lane == 0) reds[warp] = s;
    __syncthreads();
    float bs = reds[0];
#pragma unroll
    for (int i = 1; i < 8; i++) bs += reds[i];

    float inv = 1.0f / bs;
#pragma unroll
    for (int i = 0; i < VEC; i++) p[t*VEC + i] = v[i] * inv;
}

// ---------------------------------------------------------------------------
// out = LayerNorm(X + R) * g + b over last dim (D=1024). One block per row.
// ---------------------------------------------------------------------------
__global__ __launch_bounds__(256) void ln_residual_kernel(
    const float* __restrict__ X, const float* __restrict__ R,
    const float* __restrict__ g, const float* __restrict__ be,
    float* __restrict__ out)
{
    __shared__ float red[256];
    const size_t row = blockIdx.x;
    const int t = threadIdx.x;
    const float* xr = X + row*cD;
    const float* rr = R + row*cD;

    float v[4]; float s = 0.f;
#pragma unroll
    for (int i = 0; i < 4; i++) { v[i] = xr[t + i*256] + rr[t + i*256]; s += v[i]; }
    red[t] = s; __syncthreads();
    for (int k = 128; k > 0; k >>= 1) { if (t < k) red[t] += red[t+k]; __syncthreads(); }
    float mu = red[0] * (1.0f / cD); __syncthreads();

    float vs = 0.f;
#pragma unroll
    for (int i = 0; i < 4; i++) { float d = v[i] - mu; vs += d*d; }
    red[t] = vs; __syncthreads();
    for (int k = 128; k > 0; k >>= 1) { if (t < k) red[t] += red[t+k]; __syncthreads(); }
    float inv = rsqrtf(red[0] * (1.0f / cD) + 1e-5f);

    float* orow = out + row*cD;
#pragma unroll
    for (int i = 0; i < 4; i++) {
        int c = t + i*256;
        orow[c] = (v[i] - mu) * inv * g[c] + be[c];
    }
}

// ---------------------------------------------------------------------------
// Launch
// ---------------------------------------------------------------------------
extern "C" void kernel_launch(void* const* d_in, const int* in_sizes, int n_in,
                              void* d_out, int out_size)
{
    const float* x        = (const float*)d_in[0];
    const float* enc_o    = (const float*)d_in[1];
    const int*   enc_mask = (const int*)  d_in[2];
    const float* a1_wq = (const float*)d_in[3];
    const float* a1_bq = (const float*)d_in[4];
    const float* a1_wk = (const float*)d_in[5];
    const float* a1_bk = (const float*)d_in[6];
    const float* a1_wv = (const float*)d_in[7];
    const float* a1_bv = (const float*)d_in[8];
    const float* a1_wo = (const float*)d_in[9];
    const float* a1_bo = (const float*)d_in[10];
    const float* a2_wq = (const float*)d_in[11];
    const float* a2_bq = (const float*)d_in[12];
    const float* a2_wk = (const float*)d_in[13];
    const float* a2_bk = (const float*)d_in[14];
    const float* a2_wv = (const float*)d_in[15];
    const float* a2_bv = (const float*)d_in[16];
    const float* a2_wo = (const float*)d_in[17];
    const float* a2_bo = (const float*)d_in[18];
    const float* ff_w1 = (const float*)d_in[19];
    const float* ff_b1 = (const float*)d_in[20];
    const float* ff_w2 = (const float*)d_in[21];
    const float* ff_b2 = (const float*)d_in[22];
    const float* ln1_g = (const float*)d_in[23];
    const float* ln1_b = (const float*)d_in[24];
    const float* ln2_g = (const float*)d_in[25];
    const float* ln2_b = (const float*)d_in[26];
    const float* ln3_g = (const float*)d_in[27];
    const float* ln3_b = (const float*)d_in[28];

    float* out_x    = (float*)d_out;
    float* out_attn = out_x + (size_t)cB*cSQ*cD;

    float *bufQ, *bufK, *bufV, *bufS, *bufC, *bufO, *bufX1, *bufX2, *bufF;
    cudaGetSymbolAddress((void**)&bufQ,  g_bufQ);
    cudaGetSymbolAddress((void**)&bufK,  g_bufK);
    cudaGetSymbolAddress((void**)&bufV,  g_bufV);
    cudaGetSymbolAddress((void**)&bufS,  g_bufS);
    cudaGetSymbolAddress((void**)&bufC,  g_bufC);
    cudaGetSymbolAddress((void**)&bufO,  g_bufO);
    cudaGetSymbolAddress((void**)&bufX1, g_bufX1);
    cudaGetSymbolAddress((void**)&bufX2, g_bufX2);
    cudaGetSymbolAddress((void**)&bufF,  g_bufF);

    const float scale = 0.125f;   // 1/sqrt(64)
    const dim3 blk(256);
    const int M1 = cB * cSQ;      // 4096
    const int M2 = cB * cSK;      // 8192

    // ---- self-attention (causal) ----
    gemm_tf32_v3<false><<<dim3(cD/128, M1/128), blk>>>(x, a1_wq, a1_bq, bufQ, M1, cD, cD);
    gemm_tf32_v3<false><<<dim3(cD/128, M1/128), blk>>>(x, a1_wk, a1_bk, bufK, M1, cD, cD);
    gemm_tf32_v3<false><<<dim3(cD/128, M1/128), blk>>>(x, a1_wv, a1_bv, bufV, M1, cD, cD);
    qk_mma_kernel<<<dim3(cSQ/64, cSQ/64, cB*cH), blk>>>(bufQ, bufK, bufS, nullptr, cSQ, 1, scale);
    softmax_reg_kernel<2><<<cB*cH*cSQ, blk>>>(bufS);
    av_mma_kernel<<<dim3(cSQ/64, cB*cH), blk>>>(bufS, bufV, bufC, cSQ, 1);
    gemm_tf32_v3<false><<<dim3(cD/128, M1/128), blk>>>(bufC, a1_wo, a1_bo, bufO, M1, cD, cD);
    ln_residual_kernel<<<M1, blk>>>(x, bufO, ln1_g, ln1_b, bufX1);

    // ---- cross-attention (kv mask); probs go straight into d_out ----
    gemm_tf32_v3<false><<<dim3(cD/128, M1/128), blk>>>(bufX1, a2_wq, a2_bq, bufQ, M1, cD, cD);
    gemm_tf32_v3<false><<<dim3(cD/128, M2/128), blk>>>(enc_o, a2_wk, a2_bk, bufK, M2, cD, cD);
    gemm_tf32_v3<false><<<dim3(cD/128, M2/128), blk>>>(enc_o, a2_wv, a2_bv, bufV, M2, cD, cD);
    qk_mma_kernel<<<dim3(cSK/64, cSQ/64, cB*cH), blk>>>(bufQ, bufK, out_attn, enc_mask, cSK, 0, scale);
    softmax_reg_kernel<4><<<cB*cH*cSQ, blk>>>(out_attn);
    av_mma_kernel<<<dim3(cSQ/64, cB*cH), blk>>>(out_attn, bufV, bufC, cSK, 0);
    gemm_tf32_v3<false><<<dim3(cD/128, M1/128), blk>>>(bufC, a2_wo, a2_bo, bufO, M1, cD, cD);
    ln_residual_kernel<<<M1, blk>>>(bufX1, bufO, ln2_g, ln2_b, bufX2);

    // ---- feed-forward ----
    gemm_tf32_v3<true ><<<dim3(cF/128, M1/128), blk>>>(bufX2, ff_w1, ff_b1, bufF, M1, cF, cD);
    gemm_tf32_v3<false><<<dim3(cD/128, M1/128), blk>>>(bufF, ff_w2, ff_b2, bufO, M1, cD, cF);
    ln_residual_kernel<<<M1, blk>>>(bufX2, bufO, ln3_g, ln3_b, out_x);
}

// round 6
// speedup vs baseline: 1.4737x; 1.2547x over previous
#include <cuda_runtime.h>
#include <cuda_fp16.h>
#include <math.h>
#include <stdint.h>

// Problem constants
constexpr int cB  = 8;
constexpr int cSQ = 512;
constexpr int cSK = 1024;
constexpr int cD  = 1024;
constexpr int cH  = 16;
constexpr int cDK = 64;
constexpr int cF  = 4096;

// ---------------------------------------------------------------------------
// Scratch (device globals; no allocations allowed)
// ---------------------------------------------------------------------------
__device__ float g_bufQ [(size_t)cB*cSQ*cD];
__device__ float g_bufK [(size_t)cB*cSK*cD];
__device__ float g_bufV [(size_t)cB*cSK*cD];
__device__ float g_bufS [(size_t)cB*cH*cSQ*cSQ];
__device__ float g_bufC [(size_t)cB*cSQ*cD];
__device__ float g_bufO [(size_t)cB*cSQ*cD];
__device__ float g_bufX1[(size_t)cB*cSQ*cD];
__device__ float g_bufX2[(size_t)cB*cSQ*cD];
__device__ float g_bufF [(size_t)cB*cSQ*cF];

// ---------------------------------------------------------------------------
// helpers
// ---------------------------------------------------------------------------
__device__ __forceinline__ uint32_t f2tf(float f) {
    uint32_t r;
    asm("cvt.rna.tf32.f32 %0, %1;" : "=r"(r) : "f"(f));
    return r;
}

__device__ __forceinline__ void mma_tf32(float c[4],
    uint32_t a0, uint32_t a1, uint32_t a2, uint32_t a3,
    uint32_t b0, uint32_t b1)
{
    asm volatile(
        "mma.sync.aligned.m16n8k8.row.col.f32.tf32.tf32.f32 "
        "{%0,%1,%2,%3}, {%4,%5,%6,%7}, {%8,%9}, {%0,%1,%2,%3};"
        : "+f"(c[0]), "+f"(c[1]), "+f"(c[2]), "+f"(c[3])
        : "r"(a0), "r"(a1), "r"(a2), "r"(a3), "r"(b0), "r"(b1));
}

__device__ __forceinline__ void mma_f16(float c[4],
    uint32_t a0, uint32_t a1, uint32_t a2, uint32_t a3,
    uint32_t b0, uint32_t b1)
{
    asm volatile(
        "mma.sync.aligned.m16n8k16.row.col.f32.f16.f16.f32 "
        "{%0,%1,%2,%3}, {%4,%5,%6,%7}, {%8,%9}, {%0,%1,%2,%3};"
        : "+f"(c[0]), "+f"(c[1]), "+f"(c[2]), "+f"(c[3])
        : "r"(a0), "r"(a1), "r"(a2), "r"(a3), "r"(b0), "r"(b1));
}

__device__ __forceinline__ uint32_t h2u(__half2 h) {
    return *reinterpret_cast<uint32_t*>(&h);
}

// ---------------------------------------------------------------------------
// fp16 GEMM: C[M,N] = A[M,K] @ W[K,N] + bias (+ReLU), f32 accumulate.
// 128x128 block, 256 threads / 8 warps (2x4), warp tile 64x32, k-step 16.
// As2: [m][k2]  half2 (k-pairs), stride 12 half2 -> frag LDS conflict-free.
// Bs2: [k2][n]  half2 packing (B[2k2][n],B[2k2+1][n]), stride 136 half2
//      -> B frags are single conflict-free LDS.b32, no transpose needed.
// Register prefetch of the next k-tile overlaps LDG with the mma loop.
// ---------------------------------------------------------------------------
template<bool RELU>
__global__ __launch_bounds__(256, 2) void gemm_fp16(
    const float* __restrict__ A, const float* __restrict__ W,
    const float* __restrict__ bias, float* __restrict__ C,
    int M, int N, int K)
{
    __shared__ __half2 As2[128 * 12];
    __shared__ __half2 Bs2[8 * 136];

    const int tid  = threadIdx.x;
    const int bx   = blockIdx.x, by = blockIdx.y;
    const int warp = tid >> 5, lane = tid & 31;
    const int g = lane >> 2, tig = lane & 3;
    const int wm = warp >> 2;      // 0..1 -> 64 rows
    const int wn = warp & 3;       // 0..3 -> 32 cols

    // A loader: row ar (0..127), half2 k-offset ac2 (0 or 4)
    const int ar  = tid >> 1;
    const int ac2 = (tid & 1) * 4;
    const float* Asrc = A + (size_t)(by*128 + ar)*K + ac2*2;

    // B loader: k-pair row bk2 = warp (0..7), n = lane*4 .. +3
    const int bk2 = warp;
    const int bn  = lane * 4;
    const float* Bsrc0 = W + (size_t)(2*bk2    )*N + bx*128 + bn;
    const float* Bsrc1 = W + (size_t)(2*bk2 + 1)*N + bx*128 + bn;

    const int nk = K >> 4;
    float acc[4][4][4] = {};

    float4 pa0 = *(const float4*)(Asrc);
    float4 pa1 = *(const float4*)(Asrc + 4);
    float4 pb0 = *(const float4*)(Bsrc0);
    float4 pb1 = *(const float4*)(Bsrc1);

    for (int kt = 0; kt < nk; kt++) {
        // store current tile (fp32 -> half2)
        {
            __half2 a0 = __floats2half2_rn(pa0.x, pa0.y);
            __half2 a1 = __floats2half2_rn(pa0.z, pa0.w);
            __half2 a2 = __floats2half2_rn(pa1.x, pa1.y);
            __half2 a3 = __floats2half2_rn(pa1.z, pa1.w);
            *(uint4*)&As2[ar*12 + ac2] = make_uint4(h2u(a0), h2u(a1), h2u(a2), h2u(a3));

            __half2 b0 = __floats2half2_rn(pb0.x, pb1.x);
            __half2 b1 = __floats2half2_rn(pb0.y, pb1.y);
            __half2 b2 = __floats2half2_rn(pb0.z, pb1.z);
            __half2 b3 = __floats2half2_rn(pb0.w, pb1.w);
            *(uint4*)&Bs2[bk2*136 + bn] = make_uint4(h2u(b0), h2u(b1), h2u(b2), h2u(b3));
        }
        __syncthreads();

        // prefetch next tile while mma runs
        if (kt + 1 < nk) {
            const int kn = (kt + 1) << 4;
            pa0 = *(const float4*)(Asrc + kn);
            pa1 = *(const float4*)(Asrc + kn + 4);
            pb0 = *(const float4*)(Bsrc0 + (size_t)kn*N);
            pb1 = *(const float4*)(Bsrc1 + (size_t)kn*N);
        }

        uint32_t af[4][4];
#pragma unroll
        for (int mt = 0; mt < 4; mt++) {
            int r0 = wm*64 + mt*16 + g;
            af[mt][0] = *(uint32_t*)&As2[r0*12 + tig];
            af[mt][1] = *(uint32_t*)&As2[(r0 + 8)*12 + tig];
            af[mt][2] = *(uint32_t*)&As2[r0*12 + 4 + tig];
            af[mt][3] = *(uint32_t*)&As2[(r0 + 8)*12 + 4 + tig];
        }
        uint32_t bf[4][2];
#pragma unroll
        for (int nt = 0; nt < 4; nt++) {
            int n = wn*32 + nt*8 + g;
            bf[nt][0] = *(uint32_t*)&Bs2[tig*136 + n];
            bf[nt][1] = *(uint32_t*)&Bs2[(4 + tig)*136 + n];
        }
#pragma unroll
        for (int mt = 0; mt < 4; mt++)
#pragma unroll
            for (int nt = 0; nt < 4; nt++)
                mma_f16(acc[mt][nt], af[mt][0], af[mt][1], af[mt][2], af[mt][3],
                        bf[nt][0], bf[nt][1]);
        __syncthreads();
    }

#pragma unroll
    for (int mt = 0; mt < 4; mt++) {
#pragma unroll
        for (int nt = 0; nt < 4; nt++) {
            int row0 = by*128 + wm*64 + mt*16 + g;
            int col  = bx*128 + wn*32 + nt*8 + 2*tig;
            float b0 = bias[col], b1 = bias[col + 1];
            float2 v0 = { acc[mt][nt][0] + b0, acc[mt][nt][1] + b1 };
            float2 v1 = { acc[mt][nt][2] + b0, acc[mt][nt][3] + b1 };
            if (RELU) {
                v0.x = fmaxf(v0.x, 0.f); v0.y = fmaxf(v0.y, 0.f);
                v1.x = fmaxf(v1.x, 0.f); v1.y = fmaxf(v1.y, 0.f);
            }
            *(float2*)&C[(size_t)row0*N + col]       = v0;
            *(float2*)&C[(size_t)(row0 + 8)*N + col] = v1;
        }
    }
}

// ---------------------------------------------------------------------------
// QK^T via tf32 mma. Block = 64 q x 64 k. grid = (sk/64, SQ/64, B*H).
// ---------------------------------------------------------------------------
__global__ __launch_bounds__(256) void qk_mma_kernel(
    const float* __restrict__ Q, const float* __restrict__ Km,
    float* __restrict__ S, const int* __restrict__ kvmask,
    int sk, int causal, float scale)
{
    __shared__ uint32_t Qs[64 * 68];
    __shared__ uint32_t Ks[64 * 68];
    __shared__ int msk[64];

    const int bh = blockIdx.z;
    const int b  = bh >> 4, h = bh & 15;
    const int q0 = blockIdx.y * 64;
    const int k0 = blockIdx.x * 64;
    const int tid  = threadIdx.x;
    const int warp = tid >> 5, lane = tid & 31;
    const int g = lane >> 2, tig = lane & 3;
    const int wm = warp >> 2;
    const int wn = warp & 3;

    if (causal && k0 > q0 + 63) {
        float4 ninf = { -INFINITY, -INFINITY, -INFINITY, -INFINITY };
#pragma unroll
        for (int it = 0; it < 4; it++) {
            int idx = tid + it * 256;
            int r = idx >> 4, c4 = (idx & 15) * 4;
            *(float4*)(S + ((size_t)bh*cSQ + q0 + r)*sk + k0 + c4) = ninf;
        }
        return;
    }

    const float* Qbase = Q  + ((size_t)b*cSQ + q0)*cD + h*cDK;
    const float* Kbase = Km + ((size_t)b*sk  + k0)*cD + h*cDK;
#pragma unroll
    for (int it = 0; it < 4; it++) {
        int idx = tid + it * 256;
        int r = idx >> 4, c4 = (idx & 15) * 4;
        float4 v = *(const float4*)(Qbase + (size_t)r*cD + c4);
        uint4 u = { f2tf(v.x), f2tf(v.y), f2tf(v.z), f2tf(v.w) };
        *(uint4*)&Qs[r*68 + c4] = u;
        float4 w = *(const float4*)(Kbase + (size_t)r*cD + c4);
        uint4 t = { f2tf(w.x), f2tf(w.y), f2tf(w.z), f2tf(w.w) };
        *(uint4*)&Ks[r*68 + c4] = t;
    }
    if (kvmask && tid < 64) msk[tid] = kvmask[b*sk + k0 + tid];
    __syncthreads();

    float acc[2][2][4] = {};
#pragma unroll
    for (int kk = 0; kk < 64; kk += 8) {
        uint32_t bf[2][2];
#pragma unroll
        for (int nt = 0; nt < 2; nt++) {
            int n = wn*16 + nt*8 + g;
            bf[nt][0] = Ks[n*68 + kk + tig];
            bf[nt][1] = Ks[n*68 + kk + 4 + tig];
        }
        uint32_t af[2][4];
#pragma unroll
        for (int mt = 0; mt < 2; mt++) {
            int r0 = wm*32 + mt*16 + g;
            af[mt][0] = Qs[r0*68 + kk + tig];
            af[mt][1] = Qs[(r0 + 8)*68 + kk + tig];
            af[mt][2] = Qs[r0*68 + kk + 4 + tig];
            af[mt][3] = Qs[(r0 + 8)*68 + kk + 4 + tig];
        }
#pragma unroll
        for (int mt = 0; mt < 2; mt++)
#pragma unroll
            for (int nt = 0; nt < 2; nt++)
                mma_tf32(acc[mt][nt], af[mt][0], af[mt][1], af[mt][2], af[mt][3],
                         bf[nt][0], bf[nt][1]);
    }

#pragma unroll
    for (int mt = 0; mt < 2; mt++) {
#pragma unroll
        for (int nt = 0; nt < 2; nt++) {
            int qrow = q0 + wm*32 + mt*16 + g;
            int kl   = wn*16 + nt*8 + 2*tig;
            int kcol = k0 + kl;
            bool m0 = kvmask && msk[kl] == 0;
            bool m1 = kvmask && msk[kl + 1] == 0;
#pragma unroll
            for (int rr = 0; rr < 2; rr++) {
                int q = qrow + rr*8;
                float v0 = acc[mt][nt][rr*2 + 0] * scale;
                float v1 = acc[mt][nt][rr*2 + 1] * scale;
                if ((causal && kcol     > q) || m0) v0 = -INFINITY;
                if ((causal && kcol + 1 > q) || m1) v1 = -INFINITY;
                float2 v = { v0, v1 };
                *(float2*)&S[((size_t)bh*cSQ + q)*sk + kcol] = v;
            }
        }
    }
}

// ---------------------------------------------------------------------------
// A @ V via tf32 mma. Block = 64 q x 64 d (one head). grid = (SQ/64, B*H).
// ---------------------------------------------------------------------------
__global__ __launch_bounds__(256) void av_mma_kernel(
    const float* __restrict__ P, const float* __restrict__ V,
    float* __restrict__ O, int sk, int causal)
{
    __shared__ uint32_t Ps[64 * 36];
    __shared__ uint32_t Vs[32 * 72];

    const int bh = blockIdx.y;
    const int b  = bh >> 4, h = bh & 15;
    const int q0 = blockIdx.x * 64;
    const int tid  = threadIdx.x;
    const int warp = tid >> 5, lane = tid & 31;
    const int g = lane >> 2, tig = lane & 3;
    const int wm = warp >> 2;
    const int wn = warp & 3;

    const float* Pbase = P + ((size_t)bh*cSQ + q0)*sk;
    const float* Vbase = V + ((size_t)b*sk)*cD + h*cDK;

    float acc[2][2][4] = {};
    const int kend = causal ? (q0 + 64) : sk;

    for (int k0 = 0; k0 < kend; k0 += 32) {
#pragma unroll
        for (int it = 0; it < 2; it++) {
            int idx = tid + it * 256;
            {
                int r = idx >> 3, c4 = (idx & 7) * 4;
                float4 v = *(const float4*)(Pbase + (size_t)r*sk + k0 + c4);
                uint4 u = { f2tf(v.x), f2tf(v.y), f2tf(v.z), f2tf(v.w) };
                *(uint4*)&Ps[r*36 + c4] = u;
            }
            {
                int r = idx >> 4, c4 = (idx & 15) * 4;
                float4 v = *(const float4*)(Vbase + (size_t)(k0 + r)*cD + c4);
                uint4 u = { f2tf(v.x), f2tf(v.y), f2tf(v.z), f2tf(v.w) };
                *(uint4*)&Vs[r*72 + c4] = u;
            }
        }
        __syncthreads();

#pragma unroll
        for (int kk = 0; kk < 32; kk += 8) {
            uint32_t bf[2][2];
#pragma unroll
            for (int nt = 0; nt < 2; nt++) {
                int n = wn*16 + nt*8 + g;
                bf[nt][0] = Vs[(kk + tig)*72 + n];
                bf[nt][1] = Vs[(kk + 4 + tig)*72 + n];
            }
            uint32_t af[2][4];
#pragma unroll
            for (int mt = 0; mt < 2; mt++) {
                int r0 = wm*32 + mt*16 + g;
                af[mt][0] = Ps[r0*36 + kk + tig];
                af[mt][1] = Ps[(r0 + 8)*36 + kk + tig];
                af[mt][2] = Ps[r0*36 + kk + 4 + tig];
                af[mt][3] = Ps[(r0 + 8)*36 + kk + 4 + tig];
            }
#pragma unroll
            for (int mt = 0; mt < 2; mt++)
#pragma unroll
                for (int nt = 0; nt < 2; nt++)
                    mma_tf32(acc[mt][nt], af[mt][0], af[mt][1], af[mt][2], af[mt][3],
                             bf[nt][0], bf[nt][1]);
        }
        __syncthreads();
    }

#pragma unroll
    for (int mt = 0; mt < 2; mt++) {
#pragma unroll
        for (int nt = 0; nt < 2; nt++) {
            int qrow = q0 + wm*32 + mt*16 + g;
            int d    = wn*16 + nt*8 + 2*tig;
#pragma unroll
            for (int rr = 0; rr < 2; rr++) {
                size_t row = (size_t)b*cSQ + qrow + rr*8;
                float2 v = { acc[mt][nt][rr*2 + 0], acc[mt][nt][rr*2 + 1] };
                *(float2*)&O[row*cD + h*cDK + d] = v;
            }
        }
    }
}

// ---------------------------------------------------------------------------
// Register-resident row softmax. One block (256 threads) per row.
// ---------------------------------------------------------------------------
template<int VEC>
__global__ __launch_bounds__(256) void softmax_reg_kernel(float* __restrict__ S)
{
    __shared__ float redm[8];
    __shared__ float reds[8];
    float* p = S + (size_t)blockIdx.x * (256 * VEC);
    const int t = threadIdx.x;
    const int warp = t >> 5, lane = t & 31;

    float v[VEC];
#pragma unroll
    for (int i = 0; i < VEC; i++) v[i] = p[t*VEC + i];

    float m = v[0];
#pragma unroll
    for (int i = 1; i < VEC; i++) m = fmaxf(m, v[i]);
#pragma unroll
    for (int off = 16; off > 0; off >>= 1)
        m = fmaxf(m, __shfl_xor_sync(0xffffffffu, m, off));
    if (lane == 0) redm[warp] = m;
    __syncthreads();
    float bm = redm[0];
#pragma unroll
    for (int i = 1; i < 8; i++) bm = fmaxf(bm, redm[i]);

    float s = 0.f;
#pragma unroll
    for (int i = 0; i < VEC; i++) {
        v[i] = __expf(v[i] - bm);
        s += v[i];
    }
#pragma unroll
    for (int off = 16; off > 0; off >>= 1)
        s += __shfl_xor_sync(0xffffffffu, s, off);
    if (lane == 0) reds[warp] = s;
    __syncthreads();
    float bs = reds[0];
#pragma unroll
    for (int i = 1; i < 8; i++) bs += reds[i];

    float inv = 1.0f / bs;
#pragma unroll
    for (int i = 0; i < VEC; i++) p[t*VEC + i] = v[i] * inv;
}

// ---------------------------------------------------------------------------
// out = LayerNorm(X + R) * g + b over last dim (D=1024). One block per row.
// ---------------------------------------------------------------------------
__global__ __launch_bounds__(256) void ln_residual_kernel(
    const float* __restrict__ X, const float* __restrict__ R,
    const float* __restrict__ g, const float* __restrict__ be,
    float* __restrict__ out)
{
    __shared__ float red[256];
    const size_t row = blockIdx.x;
    const int t = threadIdx.x;
    const float* xr = X + row*cD;
    const float* rr = R + row*cD;

    float v[4]; float s = 0.f;
#pragma unroll
    for (int i = 0; i < 4; i++) { v[i] = xr[t + i*256] + rr[t + i*256]; s += v[i]; }
    red[t] = s; __syncthreads();
    for (int k = 128; k > 0; k >>= 1) { if (t < k) red[t] += red[t+k]; __syncthreads(); }
    float mu = red[0] * (1.0f / cD); __syncthreads();

    float vs = 0.f;
#pragma unroll
    for (int i = 0; i < 4; i++) { float d = v[i] - mu; vs += d*d; }
    red[t] = vs; __syncthreads();
    for (int k = 128; k > 0; k >>= 1) { if (t < k) red[t] += red[t+k]; __syncthreads(); }
    float inv = rsqrtf(red[0] * (1.0f / cD) + 1e-5f);

    float* orow = out + row*cD;
#pragma unroll
    for (int i = 0; i < 4; i++) {
        int c = t + i*256;
        orow[c] = (v[i] - mu) * inv * g[c] + be[c];
    }
}

// ---------------------------------------------------------------------------
// Launch
// ---------------------------------------------------------------------------
extern "C" void kernel_launch(void* const* d_in, const int* in_sizes, int n_in,
                              void* d_out, int out_size)
{
    const float* x        = (const float*)d_in[0];
    const float* enc_o    = (const float*)d_in[1];
    const int*   enc_mask = (const int*)  d_in[2];
    const float* a1_wq = (const float*)d_in[3];
    const float* a1_bq = (const float*)d_in[4];
    const float* a1_wk = (const float*)d_in[5];
    const float* a1_bk = (const float*)d_in[6];
    const float* a1_wv = (const float*)d_in[7];
    const float* a1_bv = (const float*)d_in[8];
    const float* a1_wo = (const float*)d_in[9];
    const float* a1_bo = (const float*)d_in[10];
    const float* a2_wq = (const float*)d_in[11];
    const float* a2_bq = (const float*)d_in[12];
    const float* a2_wk = (const float*)d_in[13];
    const float* a2_bk = (const float*)d_in[14];
    const float* a2_wv = (const float*)d_in[15];
    const float* a2_bv = (const float*)d_in[16];
    const float* a2_wo = (const float*)d_in[17];
    const float* a2_bo = (const float*)d_in[18];
    const float* ff_w1 = (const float*)d_in[19];
    const float* ff_b1 = (const float*)d_in[20];
    const float* ff_w2 = (const float*)d_in[21];
    const float* ff_b2 = (const float*)d_in[22];
    const float* ln1_g = (const float*)d_in[23];
    const float* ln1_b = (const float*)d_in[24];
    const float* ln2_g = (const float*)d_in[25];
    const float* ln2_b = (const float*)d_in[26];
    const float* ln3_g = (const float*)d_in[27];
    const float* ln3_b = (const float*)d_in[28];

    float* out_x    = (float*)d_out;
    float* out_attn = out_x + (size_t)cB*cSQ*cD;

    float *bufQ, *bufK, *bufV, *bufS, *bufC, *bufO, *bufX1, *bufX2, *bufF;
    cudaGetSymbolAddress((void**)&bufQ,  g_bufQ);
    cudaGetSymbolAddress((void**)&bufK,  g_bufK);
    cudaGetSymbolAddress((void**)&bufV,  g_bufV);
    cudaGetSymbolAddress((void**)&bufS,  g_bufS);
    cudaGetSymbolAddress((void**)&bufC,  g_bufC);
    cudaGetSymbolAddress((void**)&bufO,  g_bufO);
    cudaGetSymbolAddress((void**)&bufX1, g_bufX1);
    cudaGetSymbolAddress((void**)&bufX2, g_bufX2);
    cudaGetSymbolAddress((void**)&bufF,  g_bufF);

    const float scale = 0.125f;   // 1/sqrt(64)
    const dim3 blk(256);
    const int M1 = cB * cSQ;      // 4096
    const int M2 = cB * cSK;      // 8192

    // ---- self-attention (causal) ----
    gemm_fp16<false><<<dim3(cD/128, M1/128), blk>>>(x, a1_wq, a1_bq, bufQ, M1, cD, cD);
    gemm_fp16<false><<<dim3(cD/128, M1/128), blk>>>(x, a1_wk, a1_bk, bufK, M1, cD, cD);
    gemm_fp16<false><<<dim3(cD/128, M1/128), blk>>>(x, a1_wv, a1_bv, bufV, M1, cD, cD);
    qk_mma_kernel<<<dim3(cSQ/64, cSQ/64, cB*cH), blk>>>(bufQ, bufK, bufS, nullptr, cSQ, 1, scale);
    softmax_reg_kernel<2><<<cB*cH*cSQ, blk>>>(bufS);
    av_mma_kernel<<<dim3(cSQ/64, cB*cH), blk>>>(bufS, bufV, bufC, cSQ, 1);
    gemm_fp16<false><<<dim3(cD/128, M1/128), blk>>>(bufC, a1_wo, a1_bo, bufO, M1, cD, cD);
    ln_residual_kernel<<<M1, blk>>>(x, bufO, ln1_g, ln1_b, bufX1);

    // ---- cross-attention (kv mask); probs go straight into d_out ----
    gemm_fp16<false><<<dim3(cD/128, M1/128), blk>>>(bufX1, a2_wq, a2_bq, bufQ, M1, cD, cD);
    gemm_fp16<false><<<dim3(cD/128, M2/128), blk>>>(enc_o, a2_wk, a2_bk, bufK, M2, cD, cD);
    gemm_fp16<false><<<dim3(cD/128, M2/128), blk>>>(enc_o, a2_wv, a2_bv, bufV, M2, cD, cD);
    qk_mma_kernel<<<dim3(cSK/64, cSQ/64, cB*cH), blk>>>(bufQ, bufK, out_attn, enc_mask, cSK, 0, scale);
    softmax_reg_kernel<4><<<cB*cH*cSQ, blk>>>(out_attn);
    av_mma_kernel<<<dim3(cSQ/64, cB*cH), blk>>>(out_attn, bufV, bufC, cSK, 0);
    gemm_fp16<false><<<dim3(cD/128, M1/128), blk>>>(bufC, a2_wo, a2_bo, bufO, M1, cD, cD);
    ln_residual_kernel<<<M1, blk>>>(bufX1, bufO, ln2_g, ln2_b, bufX2);

    // ---- feed-forward ----
    gemm_fp16<true ><<<dim3(cF/128, M1/128), blk>>>(bufX2, ff_w1, ff_b1, bufF, M1, cF, cD);
    gemm_fp16<false><<<dim3(cD/128, M1/128), blk>>>(bufF, ff_w2, ff_b2, bufO, M1, cD, cF);
    ln_residual_kernel<<<M1, blk>>>(bufX2, bufO, ln3_g, ln3_b, out_x);
}